// round 16
// baseline (speedup 1.0000x reference)
#include <cuda_runtime.h>
#include <cuda_fp16.h>
#include <cstdint>
#include <math.h>

#define NB 2
#define NS 2048
#define NDIM 1024
#define NH 16
#define QD 64
#define VDm 96
#define NHV (NH*VDm)
#define NROWS (NB*NS)
#define WLD 1216

__device__ __half g_xn [NROWS*NDIM];
__device__ __half g_qh [NROWS*NDIM];
__device__ __half g_ql [NROWS*NDIM];
__device__ __half g_kh [NROWS*QD];
__device__ __half g_vt [VDm*NROWS];
__device__ __half g_ctx[NROWS*NHV];
__device__ __half g_wqkv[NDIM*WLD];
__device__ __half g_wo [NHV*NDIM];

__device__ __forceinline__ uint32_t smem_u32(const void* p){
    return (uint32_t)__cvta_generic_to_shared(p);
}
__device__ __forceinline__ void mma16(float c[4], const uint32_t a[4], const uint32_t b[2]){
    asm volatile("mma.sync.aligned.m16n8k16.row.col.f32.f16.f16.f32 "
        "{%0,%1,%2,%3}, {%4,%5,%6,%7}, {%8,%9}, {%0,%1,%2,%3};"
        : "+f"(c[0]), "+f"(c[1]), "+f"(c[2]), "+f"(c[3])
        : "r"(a[0]), "r"(a[1]), "r"(a[2]), "r"(a[3]), "r"(b[0]), "r"(b[1]));
}
__device__ __forceinline__ void ldsm4(uint32_t r[4], uint32_t a){
    asm volatile("ldmatrix.sync.aligned.m8n8.x4.shared.b16 {%0,%1,%2,%3}, [%4];"
        : "=r"(r[0]), "=r"(r[1]), "=r"(r[2]), "=r"(r[3]) : "r"(a));
}
__device__ __forceinline__ void ldsm4t(uint32_t r[4], uint32_t a){
    asm volatile("ldmatrix.sync.aligned.m8n8.x4.trans.shared.b16 {%0,%1,%2,%3}, [%4];"
        : "=r"(r[0]), "=r"(r[1]), "=r"(r[2]), "=r"(r[3]) : "r"(a));
}
__device__ __forceinline__ void cpa(uint32_t dst, const void* src){
    asm volatile("cp.async.cg.shared.global [%0], [%1], 16;" :: "r"(dst), "l"(src) : "memory");
}
#define CP_COMMIT() asm volatile("cp.async.commit_group;" ::: "memory")
#define CP_WAIT0()  asm volatile("cp.async.wait_group 0;" ::: "memory")
#define CP_WAIT1()  asm volatile("cp.async.wait_group 1;" ::: "memory")

__device__ __forceinline__ uint32_t packh2(float a, float b){
    __half2 h = __floats2half2_rn(a, b);
    return *(uint32_t*)&h;
}
// exp(5*tanh(z/5))/e^5  (e^5 cancels in normalization)
__device__ __forceinline__ float softcap_exp(float z){
    float t; asm("tanh.approx.f32 %0, %1;" : "=f"(t) : "f"(0.2f*z));
    return __expf(5.0f*t - 5.0f);
}

__global__ __launch_bounds__(256) void rmsnorm_kernel(const float* __restrict__ x,
                                                      const float* __restrict__ w){
    int row = blockIdx.x, t = threadIdx.x;
    float4 v = ((const float4*)(x + (size_t)row*NDIM))[t];
    float ss = v.x*v.x + v.y*v.y + v.z*v.z + v.w*v.w;
    #pragma unroll
    for (int o=16;o;o>>=1) ss += __shfl_xor_sync(0xffffffffu, ss, o);
    __shared__ float red[8];
    if ((t&31)==0) red[t>>5] = ss;
    __syncthreads();
    if (t < 32){
        float s2 = (t < 8) ? red[t] : 0.f;
        #pragma unroll
        for (int o=4;o;o>>=1) s2 += __shfl_xor_sync(0xffffffffu, s2, o);
        if (t==0) red[0] = s2;
    }
    __syncthreads();
    float sc = rsqrtf(red[0]*(1.0f/NDIM) + 1e-8f);
    float4 wv = ((const float4*)w)[t];
    __half2* dst = (__half2*)(g_xn + (size_t)row*NDIM);
    dst[2*t]   = __floats2half2_rn(v.x*wv.x*sc, v.y*wv.y*sc);
    dst[2*t+1] = __floats2half2_rn(v.z*wv.z*sc, v.w*wv.w*sc);
}

__global__ void pack_wqkv(const float* __restrict__ Wq, const float* __restrict__ Wk,
                          const float* __restrict__ Wv){
    int row = blockIdx.y, col = blockIdx.x*256 + threadIdx.x;
    if (col >= WLD) return;
    float v = 0.f;
    if (col < 1024)      v = Wq[(size_t)row*1024 + col];
    else if (col < 1088) v = Wk[(size_t)row*64 + col-1024];
    else if (col < 1184) v = Wv[(size_t)row*96 + col-1088];
    g_wqkv[(size_t)row*WLD + col] = __float2half_rn(v);
}
__global__ void conv_wo(const float* __restrict__ Wo){
    int i = blockIdx.x*256 + threadIdx.x;
    g_wo[i] = __float2half_rn(Wo[i]);
}

// fp16 GEMM: BM=128,BN=64,BK=32; 3-stage cp.async pipeline.
// MODE 0: C=A@W+bias (fp32). MODE 1: fused QKV epilogue (rope / vt).
template<int MODE>
__global__ __launch_bounds__(256) void gemm_f16(
    const __half* __restrict__ A, int lda, const __half* __restrict__ W, int ldw,
    const float* __restrict__ bias, float* __restrict__ C, int NIT)
{
    __shared__ __align__(16) __half sm[3*7424];  // stage: A 128x40 + B 32x72
    const int tid = threadIdx.x, warp = tid>>5, lane = tid&31;
    const int gid = lane>>2, tig = lane&3, mw = warp>>1, nw = warp&1;
    const int m0 = blockIdx.y*128, n0 = blockIdx.x*64;

    float acc[2][4][4];
    #pragma unroll
    for (int i=0;i<2;i++)
        #pragma unroll
        for (int j=0;j<4;j++)
            #pragma unroll
            for (int l=0;l<4;l++) acc[i][j][l]=0.f;

    #pragma unroll 1
    for (int p=0;p<2;p++){
        uint32_t ab = smem_u32(sm + p*7424), bb2 = ab + 5120*2;
        int k0 = p*32;
        #pragma unroll
        for (int i=0;i<2;i++){
            int idx = tid + 256*i, r = idx>>2, s = idx&3;
            cpa(ab + (r*40+s*8)*2, A + (size_t)(m0+r)*lda + k0 + s*8);
        }
        { int r = tid>>3, s = tid&7; cpa(bb2 + (r*72+s*8)*2, W + (size_t)(k0+r)*ldw + n0 + s*8); }
        CP_COMMIT();
    }
    for (int it=0; it<NIT; it++){
        CP_WAIT1();
        __syncthreads();
        if (it+2 < NIT){
            int st = (it+2)%3, k0 = (it+2)*32;
            uint32_t ab = smem_u32(sm + st*7424), bb2 = ab + 5120*2;
            #pragma unroll
            for (int i=0;i<2;i++){
                int idx = tid + 256*i, r = idx>>2, s = idx&3;
                cpa(ab + (r*40+s*8)*2, A + (size_t)(m0+r)*lda + k0 + s*8);
            }
            { int r = tid>>3, s = tid&7; cpa(bb2 + (r*72+s*8)*2, W + (size_t)(k0+r)*ldw + n0 + s*8); }
            CP_COMMIT();
        }
        uint32_t abase = smem_u32(sm + (it%3)*7424), bbase = abase + 5120*2;
        uint32_t aa[2][2][4], bb[4][4];
        #pragma unroll
        for (int mt=0;mt<2;mt++)
            #pragma unroll
            for (int ks=0;ks<2;ks++){
                int r = mw*32 + mt*16 + (lane&15), c = ks*16 + ((lane>>4)<<3);
                ldsm4(aa[mt][ks], abase + (r*40+c)*2);
            }
        #pragma unroll
        for (int nt=0;nt<4;nt++)
            ldsm4t(bb[nt], bbase + (lane*72 + nw*32 + nt*8)*2);
        #pragma unroll
        for (int ks=0;ks<2;ks++)
            #pragma unroll
            for (int nt=0;nt<4;nt++)
                #pragma unroll
                for (int mt=0;mt<2;mt++)
                    mma16(acc[mt][nt], aa[mt][ks], &bb[nt][ks*2]);
    }

    if (MODE == 0){
        #pragma unroll
        for (int mt=0;mt<2;mt++)
            #pragma unroll
            for (int nt=0;nt<4;nt++){
                int r0 = m0 + mw*32 + mt*16 + gid, c0 = n0 + nw*32 + nt*8 + 2*tig;
                float b0 = bias[c0], b1 = bias[c0+1];
                C[(size_t)r0*NDIM + c0]       = acc[mt][nt][0] + b0;
                C[(size_t)r0*NDIM + c0+1]     = acc[mt][nt][1] + b1;
                C[(size_t)(r0+8)*NDIM + c0]   = acc[mt][nt][2] + b0;
                C[(size_t)(r0+8)*NDIM + c0+1] = acc[mt][nt][3] + b1;
            }
    } else {
        int t = blockIdx.x;  // 0..15 Q heads, 16 K, 17..18 V
        #pragma unroll
        for (int mt=0;mt<2;mt++)
            #pragma unroll
            for (int nt=0;nt<4;nt++){
                int r0 = m0 + mw*32 + mt*16 + gid, c0 = nw*32 + nt*8 + 2*tig;
                if (t <= 16){
                    int d = c0 >> 1;
                    float freq = exp2f(-(float)d * (11.0f/31.0f));
                    #pragma unroll
                    for (int rr=0;rr<2;rr++){
                        int row = r0 + rr*8;
                        float x1 = acc[mt][nt][rr*2], x2 = acc[mt][nt][rr*2+1];
                        float st, ct;
                        sincosf((float)(row & (NS-1)) * freq, &st, &ct);
                        float o1 = x1*ct - x2*st, o2 = x1*st + x2*ct;
                        __half h1 = __float2half_rn(o1), h2 = __float2half_rn(o2);
                        if (t < 16){
                            size_t base = (size_t)row*NDIM + t*64;
                            g_qh[base+d]    = h1;
                            g_qh[base+d+32] = h2;
                            g_ql[base+d]    = __float2half_rn(o1 - __half2float(h1));
                            g_ql[base+d+32] = __float2half_rn(o2 - __half2float(h2));
                        } else {
                            size_t base = (size_t)row*QD;
                            g_kh[base+d]    = h1;
                            g_kh[base+d+32] = h2;
                        }
                    }
                } else {
                    int vc = (t-17)*64 + c0;
                    if (vc < VDm){
                        float b0 = bias[vc], b1 = bias[vc+1];
                        g_vt[(size_t)vc*NROWS + r0]       = __float2half_rn(acc[mt][nt][0]+b0);
                        g_vt[(size_t)(vc+1)*NROWS + r0]   = __float2half_rn(acc[mt][nt][1]+b1);
                        g_vt[(size_t)vc*NROWS + r0+8]     = __float2half_rn(acc[mt][nt][2]+b0);
                        g_vt[(size_t)(vc+1)*NROWS + r0+8] = __float2half_rn(acc[mt][nt][3]+b1);
                    }
                }
            }
    }
}

// attention: 64 queries x (b,h) per block, 128 thr / 4 warps, j-chunks of 64.
// stage = kh 64x72 + vt 96x72 = 11520 halfs; 2 stages static smem.
__global__ __launch_bounds__(128) void attn_kernel(const float* __restrict__ bias){
    __shared__ __align__(16) __half sm[2*11520];
    const int tid = threadIdx.x, w = tid>>5, lane = tid&31;
    const int gid = lane>>2, tig = lane&3;
    const int i0 = blockIdx.x*64, h = blockIdx.y, b = blockIdx.z;
    const int bNS = b*NS, row0 = bNS + i0 + w*16;
    const uint32_t sm0 = smem_u32(sm);

    uint32_t qh[4][4], ql[4][4];
    #pragma unroll
    for (int ks=0;ks<4;ks++){
        size_t base = (size_t)(row0+gid)*NDIM + h*QD + ks*16 + 2*tig;
        size_t base8 = base + (size_t)8*NDIM;
        qh[ks][0] = *(const uint32_t*)(g_qh + base);
        qh[ks][1] = *(const uint32_t*)(g_qh + base8);
        qh[ks][2] = *(const uint32_t*)(g_qh + base + 8);
        qh[ks][3] = *(const uint32_t*)(g_qh + base8 + 8);
        ql[ks][0] = *(const uint32_t*)(g_ql + base);
        ql[ks][1] = *(const uint32_t*)(g_ql + base8);
        ql[ks][2] = *(const uint32_t*)(g_ql + base + 8);
        ql[ks][3] = *(const uint32_t*)(g_ql + base8 + 8);
    }
    float ctx[12][4];
    #pragma unroll
    for (int nt=0;nt<12;nt++)
        #pragma unroll
        for (int r=0;r<4;r++) ctx[nt][r]=0.f;
    float rsum0 = 0.f, rsum1 = 0.f;
    const float* brow = bias + ((size_t)(b*NH+h)*NS + (i0 + w*16 + gid))*NS;

    {   // stage chunk 0
        #pragma unroll
        for (int i=0;i<4;i++){
            int idx = tid + 128*i, r = idx>>3, s = idx&7;
            cpa(sm0 + (r*72+s*8)*2, g_kh + (size_t)(bNS+r)*QD + s*8);
        }
        #pragma unroll
        for (int i=0;i<6;i++){
            int idx = tid + 128*i, r = idx>>3, s = idx&7;
            cpa(sm0 + (4608 + r*72+s*8)*2, g_vt + (size_t)r*NROWS + bNS + s*8);
        }
        CP_COMMIT();
    }

    for (int jc=0; jc<NS/64; jc++){
        CP_WAIT0();
        __syncthreads();
        if (jc+1 < NS/64){
            int j0n = (jc+1)*64;
            uint32_t sb = sm0 + ((jc+1)&1)*11520*2;
            #pragma unroll
            for (int i=0;i<4;i++){
                int idx = tid + 128*i, r = idx>>3, s = idx&7;
                cpa(sb + (r*72+s*8)*2, g_kh + (size_t)(bNS+j0n+r)*QD + s*8);
            }
            #pragma unroll
            for (int i=0;i<6;i++){
                int idx = tid + 128*i, r = idx>>3, s = idx&7;
                cpa(sb + (4608 + r*72+s*8)*2, g_vt + (size_t)r*NROWS + bNS + j0n + s*8);
            }
            CP_COMMIT();
        }
        const int j0 = jc*64;
        uint32_t cb = sm0 + (jc&1)*11520*2;

        float2 bz[8][2];
        #pragma unroll
        for (int nt=0;nt<8;nt++){
            bz[nt][0] = *(const float2*)(brow + j0 + nt*8 + 2*tig);
            bz[nt][1] = *(const float2*)(brow + (size_t)8*NS + j0 + nt*8 + 2*tig);
        }

        float S[8][4];
        #pragma unroll
        for (int nt=0;nt<8;nt++)
            #pragma unroll
            for (int r=0;r<4;r++) S[nt][r]=0.f;
        #pragma unroll
        for (int ks=0;ks<4;ks++){
            #pragma unroll
            for (int jb=0;jb<4;jb++){
                int r = jb*16 + ((lane>>4)<<3) + (lane&7);
                int c = ks*16 + ((lane>>3)&1)*8;
                uint32_t kf[4];
                ldsm4(kf, cb + (r*72+c)*2);
                mma16(S[2*jb],   qh[ks], &kf[0]);
                mma16(S[2*jb+1], qh[ks], &kf[2]);
                mma16(S[2*jb],   ql[ks], &kf[0]);
                mma16(S[2*jb+1], ql[ks], &kf[2]);
            }
        }

        // softcap-exp; P packed straight into A-fragment registers
        uint32_t pf[8][2];
        #pragma unroll
        for (int nt=0;nt<8;nt++){
            float p00 = softcap_exp(S[nt][0] + bz[nt][0].x);
            float p01 = softcap_exp(S[nt][1] + bz[nt][0].y);
            float p10 = softcap_exp(S[nt][2] + bz[nt][1].x);
            float p11 = softcap_exp(S[nt][3] + bz[nt][1].y);
            rsum0 += p00 + p01; rsum1 += p10 + p11;
            pf[nt][0] = packh2(p00, p01);
            pf[nt][1] = packh2(p10, p11);
        }

        #pragma unroll
        for (int ks=0;ks<4;ks++){
            uint32_t pa[4] = {pf[2*ks][0], pf[2*ks][1], pf[2*ks+1][0], pf[2*ks+1][1]};
            #pragma unroll
            for (int cbk=0;cbk<6;cbk++){
                int r = cbk*16 + ((lane>>4)<<3) + (lane&7);
                int c = ks*16 + ((lane>>3)&1)*8;
                uint32_t vf[4];
                ldsm4(vf, cb + (4608 + r*72+c)*2);
                mma16(ctx[2*cbk],   pa, &vf[0]);
                mma16(ctx[2*cbk+1], pa, &vf[2]);
            }
        }
    }

    rsum0 += __shfl_xor_sync(0xffffffffu, rsum0, 1);
    rsum0 += __shfl_xor_sync(0xffffffffu, rsum0, 2);
    rsum1 += __shfl_xor_sync(0xffffffffu, rsum1, 1);
    rsum1 += __shfl_xor_sync(0xffffffffu, rsum1, 2);
    float inv0 = 1.f/rsum0, inv1 = 1.f/rsum1;
    int orow = row0 + gid;
    #pragma unroll
    for (int nt=0;nt<12;nt++){
        int col = h*VDm + nt*8 + 2*tig;
        *(__half2*)(g_ctx + (size_t)orow*NHV + col) =
            __floats2half2_rn(ctx[nt][0]*inv0, ctx[nt][1]*inv0);
        *(__half2*)(g_ctx + (size_t)(orow+8)*NHV + col) =
            __floats2half2_rn(ctx[nt][2]*inv1, ctx[nt][3]*inv1);
    }
}

extern "C" void kernel_launch(void* const* d_in, const int* in_sizes, int n_in,
                              void* d_out, int out_size) {
    const float* x    = (const float*)d_in[0];
    const float* ab   = (const float*)d_in[1];
    const float* rmsw = (const float*)d_in[2];
    const float* Wq   = (const float*)d_in[3];
    const float* Wk   = (const float*)d_in[4];
    const float* Wv   = (const float*)d_in[5];
    const float* bv   = (const float*)d_in[6];
    const float* Wo   = (const float*)d_in[7];
    const float* bo   = (const float*)d_in[8];
    float* out = (float*)d_out;

    __half *xn, *ctx, *wqkv, *wo;
    cudaGetSymbolAddress((void**)&xn,   g_xn);
    cudaGetSymbolAddress((void**)&ctx,  g_ctx);
    cudaGetSymbolAddress((void**)&wqkv, g_wqkv);
    cudaGetSymbolAddress((void**)&wo,   g_wo);

    rmsnorm_kernel<<<NROWS, 256>>>(x, rmsw);
    pack_wqkv<<<dim3(5, NDIM), 256>>>(Wq, Wk, Wv);
    conv_wo<<<(NHV*NDIM)/256, 256>>>(Wo);

    gemm_f16<1><<<dim3(19, NROWS/128), 256>>>(xn, NDIM, wqkv, WLD, bv, nullptr, 32);

    attn_kernel<<<dim3(NS/64, NH, NB), 128>>>(ab);

    gemm_f16<0><<<dim3(NDIM/64, NROWS/128), 256>>>(ctx, NHV, wo, NDIM, bo, out, 48);
}

// round 17
// speedup vs baseline: 1.0155x; 1.0155x over previous
#include <cuda_runtime.h>
#include <cuda_fp16.h>
#include <cstdint>
#include <math.h>

#define NB 2
#define NS 2048
#define NDIM 1024
#define NH 16
#define QD 64
#define VDm 96
#define NHV (NH*VDm)
#define NROWS (NB*NS)
#define WLD 1216

__device__ __half g_xn [NROWS*NDIM];
__device__ __half g_qh [NROWS*NDIM];
__device__ __half g_ql [NROWS*NDIM];
__device__ __half g_kh [NROWS*QD];
__device__ __half g_vt [VDm*NROWS];
__device__ __half g_ctx[NROWS*NHV];
__device__ __half g_wqkv[NDIM*WLD];
__device__ __half g_wo [NHV*NDIM];

__device__ __forceinline__ uint32_t smem_u32(const void* p){
    return (uint32_t)__cvta_generic_to_shared(p);
}
__device__ __forceinline__ void mma16(float c[4], const uint32_t a[4], const uint32_t b[2]){
    asm volatile("mma.sync.aligned.m16n8k16.row.col.f32.f16.f16.f32 "
        "{%0,%1,%2,%3}, {%4,%5,%6,%7}, {%8,%9}, {%0,%1,%2,%3};"
        : "+f"(c[0]), "+f"(c[1]), "+f"(c[2]), "+f"(c[3])
        : "r"(a[0]), "r"(a[1]), "r"(a[2]), "r"(a[3]), "r"(b[0]), "r"(b[1]));
}
__device__ __forceinline__ void ldsm4(uint32_t r[4], uint32_t a){
    asm volatile("ldmatrix.sync.aligned.m8n8.x4.shared.b16 {%0,%1,%2,%3}, [%4];"
        : "=r"(r[0]), "=r"(r[1]), "=r"(r[2]), "=r"(r[3]) : "r"(a));
}
__device__ __forceinline__ void ldsm4t(uint32_t r[4], uint32_t a){
    asm volatile("ldmatrix.sync.aligned.m8n8.x4.trans.shared.b16 {%0,%1,%2,%3}, [%4];"
        : "=r"(r[0]), "=r"(r[1]), "=r"(r[2]), "=r"(r[3]) : "r"(a));
}
__device__ __forceinline__ void cpa(uint32_t dst, const void* src){
    asm volatile("cp.async.cg.shared.global [%0], [%1], 16;" :: "r"(dst), "l"(src) : "memory");
}
#define CP_COMMIT() asm volatile("cp.async.commit_group;" ::: "memory")
#define CP_WAIT0()  asm volatile("cp.async.wait_group 0;" ::: "memory")
#define CP_WAIT1()  asm volatile("cp.async.wait_group 1;" ::: "memory")

__device__ __forceinline__ uint32_t packh2(float a, float b){
    __half2 h = __floats2half2_rn(a, b);
    return *(uint32_t*)&h;
}
// exp(5*tanh(z/5))/e^5  (e^5 cancels in normalization)
__device__ __forceinline__ float softcap_exp(float z){
    float t; asm("tanh.approx.f32 %0, %1;" : "=f"(t) : "f"(0.2f*z));
    return __expf(5.0f*t - 5.0f);
}

__global__ __launch_bounds__(256) void rmsnorm_kernel(const float* __restrict__ x,
                                                      const float* __restrict__ w){
    int row = blockIdx.x, t = threadIdx.x;
    float4 v = ((const float4*)(x + (size_t)row*NDIM))[t];
    float ss = v.x*v.x + v.y*v.y + v.z*v.z + v.w*v.w;
    #pragma unroll
    for (int o=16;o;o>>=1) ss += __shfl_xor_sync(0xffffffffu, ss, o);
    __shared__ float red[8];
    if ((t&31)==0) red[t>>5] = ss;
    __syncthreads();
    if (t < 32){
        float s2 = (t < 8) ? red[t] : 0.f;
        #pragma unroll
        for (int o=4;o;o>>=1) s2 += __shfl_xor_sync(0xffffffffu, s2, o);
        if (t==0) red[0] = s2;
    }
    __syncthreads();
    float sc = rsqrtf(red[0]*(1.0f/NDIM) + 1e-8f);
    float4 wv = ((const float4*)w)[t];
    __half2* dst = (__half2*)(g_xn + (size_t)row*NDIM);
    dst[2*t]   = __floats2half2_rn(v.x*wv.x*sc, v.y*wv.y*sc);
    dst[2*t+1] = __floats2half2_rn(v.z*wv.z*sc, v.w*wv.w*sc);
}

__global__ void pack_wqkv(const float* __restrict__ Wq, const float* __restrict__ Wk,
                          const float* __restrict__ Wv){
    int row = blockIdx.y, col = blockIdx.x*256 + threadIdx.x;
    if (col >= WLD) return;
    float v = 0.f;
    if (col < 1024)      v = Wq[(size_t)row*1024 + col];
    else if (col < 1088) v = Wk[(size_t)row*64 + col-1024];
    else if (col < 1184) v = Wv[(size_t)row*96 + col-1088];
    g_wqkv[(size_t)row*WLD + col] = __float2half_rn(v);
}
__global__ void conv_wo(const float* __restrict__ Wo){
    int i = blockIdx.x*256 + threadIdx.x;
    g_wo[i] = __float2half_rn(Wo[i]);
}

// fp16 GEMM: BM=128,BN=64,BK=32; 3-stage cp.async pipeline.
// MODE 0: C=A@W+bias (fp32). MODE 1: fused QKV epilogue (rope / vt).
template<int MODE>
__global__ __launch_bounds__(256) void gemm_f16(
    const __half* __restrict__ A, int lda, const __half* __restrict__ W, int ldw,
    const float* __restrict__ bias, float* __restrict__ C, int NIT)
{
    __shared__ __align__(16) __half sm[3*7424];  // stage: A 128x40 + B 32x72
    const int tid = threadIdx.x, warp = tid>>5, lane = tid&31;
    const int gid = lane>>2, tig = lane&3, mw = warp>>1, nw = warp&1;
    const int m0 = blockIdx.y*128, n0 = blockIdx.x*64;

    float acc[2][4][4];
    #pragma unroll
    for (int i=0;i<2;i++)
        #pragma unroll
        for (int j=0;j<4;j++)
            #pragma unroll
            for (int l=0;l<4;l++) acc[i][j][l]=0.f;

    #pragma unroll 1
    for (int p=0;p<2;p++){
        uint32_t ab = smem_u32(sm + p*7424), bb2 = ab + 5120*2;
        int k0 = p*32;
        #pragma unroll
        for (int i=0;i<2;i++){
            int idx = tid + 256*i, r = idx>>2, s = idx&3;
            cpa(ab + (r*40+s*8)*2, A + (size_t)(m0+r)*lda + k0 + s*8);
        }
        { int r = tid>>3, s = tid&7; cpa(bb2 + (r*72+s*8)*2, W + (size_t)(k0+r)*ldw + n0 + s*8); }
        CP_COMMIT();
    }
    for (int it=0; it<NIT; it++){
        CP_WAIT1();
        __syncthreads();
        if (it+2 < NIT){
            int st = (it+2)%3, k0 = (it+2)*32;
            uint32_t ab = smem_u32(sm + st*7424), bb2 = ab + 5120*2;
            #pragma unroll
            for (int i=0;i<2;i++){
                int idx = tid + 256*i, r = idx>>2, s = idx&3;
                cpa(ab + (r*40+s*8)*2, A + (size_t)(m0+r)*lda + k0 + s*8);
            }
            { int r = tid>>3, s = tid&7; cpa(bb2 + (r*72+s*8)*2, W + (size_t)(k0+r)*ldw + n0 + s*8); }
            CP_COMMIT();
        }
        uint32_t abase = smem_u32(sm + (it%3)*7424), bbase = abase + 5120*2;
        uint32_t aa[2][2][4], bb[4][4];
        #pragma unroll
        for (int mt=0;mt<2;mt++)
            #pragma unroll
            for (int ks=0;ks<2;ks++){
                int r = mw*32 + mt*16 + (lane&15), c = ks*16 + ((lane>>4)<<3);
                ldsm4(aa[mt][ks], abase + (r*40+c)*2);
            }
        #pragma unroll
        for (int nt=0;nt<4;nt++)
            ldsm4t(bb[nt], bbase + (lane*72 + nw*32 + nt*8)*2);
        #pragma unroll
        for (int ks=0;ks<2;ks++)
            #pragma unroll
            for (int nt=0;nt<4;nt++)
                #pragma unroll
                for (int mt=0;mt<2;mt++)
                    mma16(acc[mt][nt], aa[mt][ks], &bb[nt][ks*2]);
    }

    if (MODE == 0){
        #pragma unroll
        for (int mt=0;mt<2;mt++)
            #pragma unroll
            for (int nt=0;nt<4;nt++){
                int r0 = m0 + mw*32 + mt*16 + gid, c0 = n0 + nw*32 + nt*8 + 2*tig;
                float b0 = bias[c0], b1 = bias[c0+1];
                C[(size_t)r0*NDIM + c0]       = acc[mt][nt][0] + b0;
                C[(size_t)r0*NDIM + c0+1]     = acc[mt][nt][1] + b1;
                C[(size_t)(r0+8)*NDIM + c0]   = acc[mt][nt][2] + b0;
                C[(size_t)(r0+8)*NDIM + c0+1] = acc[mt][nt][3] + b1;
            }
    } else {
        int t = blockIdx.x;  // 0..15 Q heads, 16 K, 17..18 V
        #pragma unroll
        for (int mt=0;mt<2;mt++)
            #pragma unroll
            for (int nt=0;nt<4;nt++){
                int r0 = m0 + mw*32 + mt*16 + gid, c0 = nw*32 + nt*8 + 2*tig;
                if (t <= 16){
                    int d = c0 >> 1;
                    float freq = exp2f(-(float)d * (11.0f/31.0f));
                    #pragma unroll
                    for (int rr=0;rr<2;rr++){
                        int row = r0 + rr*8;
                        float x1 = acc[mt][nt][rr*2], x2 = acc[mt][nt][rr*2+1];
                        float st, ct;
                        sincosf((float)(row & (NS-1)) * freq, &st, &ct);
                        float o1 = x1*ct - x2*st, o2 = x1*st + x2*ct;
                        __half h1 = __float2half_rn(o1), h2 = __float2half_rn(o2);
                        if (t < 16){
                            size_t base = (size_t)row*NDIM + t*64;
                            g_qh[base+d]    = h1;
                            g_qh[base+d+32] = h2;
                            g_ql[base+d]    = __float2half_rn(o1 - __half2float(h1));
                            g_ql[base+d+32] = __float2half_rn(o2 - __half2float(h2));
                        } else {
                            size_t base = (size_t)row*QD;
                            g_kh[base+d]    = h1;
                            g_kh[base+d+32] = h2;
                        }
                    }
                } else {
                    int vc = (t-17)*64 + c0;
                    if (vc < VDm){
                        float b0 = bias[vc], b1 = bias[vc+1];
                        g_vt[(size_t)vc*NROWS + r0]       = __float2half_rn(acc[mt][nt][0]+b0);
                        g_vt[(size_t)(vc+1)*NROWS + r0]   = __float2half_rn(acc[mt][nt][1]+b1);
                        g_vt[(size_t)vc*NROWS + r0+8]     = __float2half_rn(acc[mt][nt][2]+b0);
                        g_vt[(size_t)(vc+1)*NROWS + r0+8] = __float2half_rn(acc[mt][nt][3]+b1);
                    }
                }
            }
    }
}

// attention: 64 queries x (b,h) per block, 128 thr / 4 warps, j-chunks of 64.
// stage = kh 64x72 + vt 96x72 = 11520 halfs; 2 stages static smem.
__global__ __launch_bounds__(128) void attn_kernel(const float* __restrict__ bias){
    __shared__ __align__(16) __half sm[2*11520];
    const int tid = threadIdx.x, w = tid>>5, lane = tid&31;
    const int gid = lane>>2, tig = lane&3;
    const int i0 = blockIdx.x*64, h = blockIdx.y, b = blockIdx.z;
    const int bNS = b*NS, row0 = bNS + i0 + w*16;
    const uint32_t sm0 = smem_u32(sm);

    uint32_t qh[4][4], ql[4][4];
    #pragma unroll
    for (int ks=0;ks<4;ks++){
        size_t base = (size_t)(row0+gid)*NDIM + h*QD + ks*16 + 2*tig;
        size_t base8 = base + (size_t)8*NDIM;
        qh[ks][0] = *(const uint32_t*)(g_qh + base);
        qh[ks][1] = *(const uint32_t*)(g_qh + base8);
        qh[ks][2] = *(const uint32_t*)(g_qh + base + 8);
        qh[ks][3] = *(const uint32_t*)(g_qh + base8 + 8);
        ql[ks][0] = *(const uint32_t*)(g_ql + base);
        ql[ks][1] = *(const uint32_t*)(g_ql + base8);
        ql[ks][2] = *(const uint32_t*)(g_ql + base + 8);
        ql[ks][3] = *(const uint32_t*)(g_ql + base8 + 8);
    }
    float ctx[12][4];
    #pragma unroll
    for (int nt=0;nt<12;nt++)
        #pragma unroll
        for (int r=0;r<4;r++) ctx[nt][r]=0.f;
    float rsum0 = 0.f, rsum1 = 0.f;
    const float* brow = bias + ((size_t)(b*NH+h)*NS + (i0 + w*16 + gid))*NS;

    {   // stage chunk 0
        #pragma unroll
        for (int i=0;i<4;i++){
            int idx = tid + 128*i, r = idx>>3, s = idx&7;
            cpa(sm0 + (r*72+s*8)*2, g_kh + (size_t)(bNS+r)*QD + s*8);
        }
        #pragma unroll
        for (int i=0;i<6;i++){
            int idx = tid + 128*i, r = idx>>3, s = idx&7;
            cpa(sm0 + (4608 + r*72+s*8)*2, g_vt + (size_t)r*NROWS + bNS + s*8);
        }
        CP_COMMIT();
    }

    for (int jc=0; jc<NS/64; jc++){
        CP_WAIT0();
        __syncthreads();
        if (jc+1 < NS/64){
            int j0n = (jc+1)*64;
            uint32_t sb = sm0 + ((jc+1)&1)*11520*2;
            #pragma unroll
            for (int i=0;i<4;i++){
                int idx = tid + 128*i, r = idx>>3, s = idx&7;
                cpa(sb + (r*72+s*8)*2, g_kh + (size_t)(bNS+j0n+r)*QD + s*8);
            }
            #pragma unroll
            for (int i=0;i<6;i++){
                int idx = tid + 128*i, r = idx>>3, s = idx&7;
                cpa(sb + (4608 + r*72+s*8)*2, g_vt + (size_t)r*NROWS + bNS + j0n + s*8);
            }
            CP_COMMIT();
        }
        const int j0 = jc*64;
        uint32_t cb = sm0 + (jc&1)*11520*2;

        float2 bz[8][2];
        #pragma unroll
        for (int nt=0;nt<8;nt++){
            bz[nt][0] = *(const float2*)(brow + j0 + nt*8 + 2*tig);
            bz[nt][1] = *(const float2*)(brow + (size_t)8*NS + j0 + nt*8 + 2*tig);
        }

        float S[8][4];
        #pragma unroll
        for (int nt=0;nt<8;nt++)
            #pragma unroll
            for (int r=0;r<4;r++) S[nt][r]=0.f;
        #pragma unroll
        for (int ks=0;ks<4;ks++){
            #pragma unroll
            for (int jb=0;jb<4;jb++){
                int r = jb*16 + ((lane>>4)<<3) + (lane&7);
                int c = ks*16 + ((lane>>3)&1)*8;
                uint32_t kf[4];
                ldsm4(kf, cb + (r*72+c)*2);
                mma16(S[2*jb],   qh[ks], &kf[0]);
                mma16(S[2*jb+1], qh[ks], &kf[2]);
                mma16(S[2*jb],   ql[ks], &kf[0]);
                mma16(S[2*jb+1], ql[ks], &kf[2]);
            }
        }

        // softcap-exp; P packed straight into A-fragment registers
        uint32_t pf[8][2];
        #pragma unroll
        for (int nt=0;nt<8;nt++){
            float p00 = softcap_exp(S[nt][0] + bz[nt][0].x);
            float p01 = softcap_exp(S[nt][1] + bz[nt][0].y);
            float p10 = softcap_exp(S[nt][2] + bz[nt][1].x);
            float p11 = softcap_exp(S[nt][3] + bz[nt][1].y);
            rsum0 += p00 + p01; rsum1 += p10 + p11;
            pf[nt][0] = packh2(p00, p01);
            pf[nt][1] = packh2(p10, p11);
        }

        #pragma unroll
        for (int ks=0;ks<4;ks++){
            uint32_t pa[4] = {pf[2*ks][0], pf[2*ks][1], pf[2*ks+1][0], pf[2*ks+1][1]};
            #pragma unroll
            for (int cbk=0;cbk<6;cbk++){
                int r = cbk*16 + ((lane>>4)<<3) + (lane&7);
                int c = ks*16 + ((lane>>3)&1)*8;
                uint32_t vf[4];
                ldsm4(vf, cb + (4608 + r*72+c)*2);
                mma16(ctx[2*cbk],   pa, &vf[0]);
                mma16(ctx[2*cbk+1], pa, &vf[2]);
            }
        }
    }

    rsum0 += __shfl_xor_sync(0xffffffffu, rsum0, 1);
    rsum0 += __shfl_xor_sync(0xffffffffu, rsum0, 2);
    rsum1 += __shfl_xor_sync(0xffffffffu, rsum1, 1);
    rsum1 += __shfl_xor_sync(0xffffffffu, rsum1, 2);
    float inv0 = 1.f/rsum0, inv1 = 1.f/rsum1;
    int orow = row0 + gid;
    #pragma unroll
    for (int nt=0;nt<12;nt++){
        int col = h*VDm + nt*8 + 2*tig;
        *(__half2*)(g_ctx + (size_t)orow*NHV + col) =
            __floats2half2_rn(ctx[nt][0]*inv0, ctx[nt][1]*inv0);
        *(__half2*)(g_ctx + (size_t)(orow+8)*NHV + col) =
            __floats2half2_rn(ctx[nt][2]*inv1, ctx[nt][3]*inv1);
    }
}

extern "C" void kernel_launch(void* const* d_in, const int* in_sizes, int n_in,
                              void* d_out, int out_size) {
    const float* x    = (const float*)d_in[0];
    const float* ab   = (const float*)d_in[1];
    const float* rmsw = (const float*)d_in[2];
    const float* Wq   = (const float*)d_in[3];
    const float* Wk   = (const float*)d_in[4];
    const float* Wv   = (const float*)d_in[5];
    const float* bv   = (const float*)d_in[6];
    const float* Wo   = (const float*)d_in[7];
    const float* bo   = (const float*)d_in[8];
    float* out = (float*)d_out;

    __half *xn, *ctx, *wqkv, *wo;
    cudaGetSymbolAddress((void**)&xn,   g_xn);
    cudaGetSymbolAddress((void**)&ctx,  g_ctx);
    cudaGetSymbolAddress((void**)&wqkv, g_wqkv);
    cudaGetSymbolAddress((void**)&wo,   g_wo);

    rmsnorm_kernel<<<NROWS, 256>>>(x, rmsw);
    pack_wqkv<<<dim3(5, NDIM), 256>>>(Wq, Wk, Wv);
    conv_wo<<<(NHV*NDIM)/256, 256>>>(Wo);

    gemm_f16<1><<<dim3(19, NROWS/128), 256>>>(xn, NDIM, wqkv, WLD, bv, nullptr, 32);

    attn_kernel<<<dim3(NS/64, NH, NB), 128>>>(ab);

    gemm_f16<0><<<dim3(NDIM/64, NROWS/128), 256>>>(ctx, NHV, wo, NDIM, bo, out, 48);
}